// round 1
// baseline (speedup 1.0000x reference)
#include <cuda_runtime.h>
#include <cuda_bf16.h>
#include <stdint.h>

#define BATCH  32
#define TFR    8
#define HH     14
#define WWD    14
#define CDIM   768
#define CADIM  384
#define LTOK   196
#define LFULL  197
#define MROWS  (BATCH*TFR*LTOK)   // 50176

// Scratch (no allocations allowed) — zero-init BSS device globals.
__device__ __nv_bfloat16 g_h1[(size_t)MROWS * CADIM];
__device__ __nv_bfloat16 g_h2[(size_t)MROWS * CADIM];
__device__ __nv_bfloat16 g_W1b[CADIM * CDIM];
__device__ __nv_bfloat16 g_W2b[CDIM * CADIM];

// ---------------------------------------------------------------------------
// Weight conversion fp32 -> bf16 (both GEMM weight matrices, same elem count)
// ---------------------------------------------------------------------------
__global__ void cvt_weights(const float* __restrict__ W1, const float* __restrict__ W2) {
    int i = blockIdx.x * 256 + threadIdx.x;
    if (i < CADIM * CDIM) {
        g_W1b[i] = __float2bfloat16(W1[i]);
        g_W2b[i] = __float2bfloat16(W2[i]);
    }
}

// ---------------------------------------------------------------------------
// CLS token rows: out = x  (256 rows x 768)
// ---------------------------------------------------------------------------
__global__ void copy_cls(const float* __restrict__ x, float* __restrict__ out) {
    int i = blockIdx.x * 256 + threadIdx.x;
    if (i < BATCH * TFR * CDIM) {
        int bt = i / CDIM, c = i - bt * CDIM;
        size_t off = (size_t)bt * LFULL * CDIM + c;
        out[off] = x[off];
    }
}

// ---------------------------------------------------------------------------
// GEMM1: h1[M,384] = bf16( x_tok[M,768] @ W1^T + b1 )
// A fp32 (strided token rows, converted to bf16 at smem store), B bf16.
// Tile 128x128x32, 8 warps (2x4), warp tile 64x32, mma.m16n8k16.
// ---------------------------------------------------------------------------
__global__ __launch_bounds__(256, 2)
void gemm1(const float* __restrict__ x, const float* __restrict__ b1) {
    __shared__ __nv_bfloat16 As[128 * 40];
    __shared__ __nv_bfloat16 Bs[128 * 40];

    const int tid  = threadIdx.x;
    const int lane = tid & 31;
    const int warp = tid >> 5;
    const int wm   = warp >> 2;      // 0..1
    const int wn   = warp & 3;       // 0..3
    const int bm   = blockIdx.x * 128;
    const int bn   = blockIdx.y * 128;

    // A: 128 rows x 32 fp32 per k-tile; 2 threads/row, 4 float4 each.
    const int arow  = tid >> 1;
    const int acol0 = (tid & 1) * 16;
    const int growA = bm + arow;
    const int bt    = growA / LTOK;
    const int ltk   = growA - bt * LTOK;
    const float* aptr = x + ((size_t)bt * LFULL + 1 + ltk) * CDIM + acol0;

    // B: 128 n-rows x 32 bf16 per k-tile; 2 threads/row, 2 uint4 each.
    const __nv_bfloat16* bptr = g_W1b + (size_t)(bn + (tid >> 1)) * CDIM + (tid & 1) * 16;
    const int brow  = tid >> 1;
    const int bcol0 = (tid & 1) * 16;

    float acc[4][4][4];
#pragma unroll
    for (int i = 0; i < 4; i++)
#pragma unroll
        for (int j = 0; j < 4; j++)
#pragma unroll
            for (int k = 0; k < 4; k++) acc[i][j][k] = 0.f;

    const uint32_t as_base = (uint32_t)__cvta_generic_to_shared(As);
    const uint32_t bs_base = (uint32_t)__cvta_generic_to_shared(Bs);

    for (int kt = 0; kt < CDIM; kt += 32) {
        float4 av[4];
#pragma unroll
        for (int j = 0; j < 4; j++) av[j] = *(const float4*)(aptr + kt + j * 4);
        uint4 bv[2];
#pragma unroll
        for (int j = 0; j < 2; j++) bv[j] = *(const uint4*)(bptr + kt + j * 8);

        __syncthreads();
#pragma unroll
        for (int j = 0; j < 4; j++) {
            __nv_bfloat162 p0 = __floats2bfloat162_rn(av[j].x, av[j].y);
            __nv_bfloat162 p1 = __floats2bfloat162_rn(av[j].z, av[j].w);
            uint2 u;
            u.x = *(uint32_t*)&p0;
            u.y = *(uint32_t*)&p1;
            *(uint2*)&As[arow * 40 + acol0 + j * 4] = u;
        }
#pragma unroll
        for (int j = 0; j < 2; j++)
            *(uint4*)&Bs[brow * 40 + bcol0 + j * 8] = bv[j];
        __syncthreads();

#pragma unroll
        for (int ks = 0; ks < 2; ks++) {
            const int kk = ks * 16;
            uint32_t a[4][4], b[4][2];
#pragma unroll
            for (int mf = 0; mf < 4; mf++) {
                int row = wm * 64 + mf * 16 + (lane & 15);
                int col = kk + (lane >> 4) * 8;
                uint32_t addr = as_base + (uint32_t)(row * 40 + col) * 2;
                asm volatile("ldmatrix.sync.aligned.m8n8.x4.shared.b16 {%0,%1,%2,%3}, [%4];\n"
                    : "=r"(a[mf][0]), "=r"(a[mf][1]), "=r"(a[mf][2]), "=r"(a[mf][3]) : "r"(addr));
            }
#pragma unroll
            for (int nf = 0; nf < 4; nf++) {
                int row = wn * 32 + nf * 8 + (lane & 7);
                int col = kk + ((lane >> 3) & 1) * 8;
                uint32_t addr = bs_base + (uint32_t)(row * 40 + col) * 2;
                asm volatile("ldmatrix.sync.aligned.m8n8.x2.shared.b16 {%0,%1}, [%2];\n"
                    : "=r"(b[nf][0]), "=r"(b[nf][1]) : "r"(addr));
            }
#pragma unroll
            for (int mf = 0; mf < 4; mf++)
#pragma unroll
                for (int nf = 0; nf < 4; nf++)
                    asm volatile("mma.sync.aligned.m16n8k16.row.col.f32.bf16.bf16.f32 "
                        "{%0,%1,%2,%3}, {%4,%5,%6,%7}, {%8,%9}, {%0,%1,%2,%3};\n"
                        : "+f"(acc[mf][nf][0]), "+f"(acc[mf][nf][1]),
                          "+f"(acc[mf][nf][2]), "+f"(acc[mf][nf][3])
                        : "r"(a[mf][0]), "r"(a[mf][1]), "r"(a[mf][2]), "r"(a[mf][3]),
                          "r"(b[nf][0]), "r"(b[nf][1]));
        }
    }

    // Epilogue: + bias, cast bf16, store contiguous h1[M,384]
#pragma unroll
    for (int mf = 0; mf < 4; mf++) {
        int r0 = bm + wm * 64 + mf * 16 + (lane >> 2);
#pragma unroll
        for (int nf = 0; nf < 4; nf++) {
            int col = bn + wn * 32 + nf * 8 + (lane & 3) * 2;
            float bb0 = b1[col], bb1 = b1[col + 1];
            __nv_bfloat162 v0 = __floats2bfloat162_rn(acc[mf][nf][0] + bb0, acc[mf][nf][1] + bb1);
            __nv_bfloat162 v1 = __floats2bfloat162_rn(acc[mf][nf][2] + bb0, acc[mf][nf][3] + bb1);
            *(uint32_t*)&g_h1[(size_t)r0 * CADIM + col]       = *(uint32_t*)&v0;
            *(uint32_t*)&g_h1[(size_t)(r0 + 8) * CADIM + col] = *(uint32_t*)&v1;
        }
    }
}

// ---------------------------------------------------------------------------
// Depthwise 3x3x3 conv over (t,h,w) per channel; channels-last bf16.
// Block: (c-chunk 16, t-tile 2, batch b). Smem tile 4x16x16x16 bf16 = 32KB.
// Thread: channel-pair (bf16x2) x spatial strip; weights in registers.
// ---------------------------------------------------------------------------
__global__ __launch_bounds__(256)
void dwconv(const float* __restrict__ cw, const float* __restrict__ cb) {
    __shared__ __nv_bfloat16 tile[4 * 16 * 16 * 16];   // [tz][y][x][c16]
    const int tid = threadIdx.x;
    const int c0  = blockIdx.x * 16;
    const int t0  = blockIdx.y * 2;
    const int b   = blockIdx.z;

    uint32_t* tw = (uint32_t*)tile;
    for (int i = tid; i < 8192; i += 256) {      // 4*16*16*8 words
        int cp = i & 7;
        int xx = (i >> 3) & 15;
        int yy = (i >> 7) & 15;
        int tz = i >> 11;
        int t = t0 + tz - 1, h = yy - 1, w = xx - 1;
        uint32_t v = 0;
        if ((unsigned)t < 8u && (unsigned)h < 14u && (unsigned)w < 14u) {
            size_t off = ((size_t)((b * 8 + t) * 196 + h * 14 + w)) * CADIM + c0 + cp * 2;
            v = *(const uint32_t*)&g_h1[off];
        }
        tw[i] = v;
    }
    __syncthreads();

    const int cp = tid & 7;
    const int g  = tid >> 3;          // 32 spatial groups
    const int c  = c0 + cp * 2;
    float w0[27], w1[27];
#pragma unroll
    for (int j = 0; j < 27; j++) {
        w0[j] = cw[c * 27 + j];
        w1[j] = cw[(c + 1) * 27 + j];
    }
    const float cb0 = cb[c], cb1 = cb[c + 1];

    for (int sp = g; sp < 392; sp += 32) {       // 2 t x 196 hw per block
        int w  = sp % 14;
        int h  = (sp / 14) % 14;
        int tt = sp / 196;
        float a0 = cb0, a1 = cb1;
#pragma unroll
        for (int dt = 0; dt < 3; dt++)
#pragma unroll
            for (int dh = 0; dh < 3; dh++)
#pragma unroll
                for (int dw = 0; dw < 3; dw++) {
                    const int idx = dt * 9 + dh * 3 + dw;
                    uint32_t v = tw[(((tt + dt) * 16 + (h + dh)) * 16 + (w + dw)) * 8 + cp];
                    float2 f = __bfloat1622float2(*(__nv_bfloat162*)&v);
                    a0 += f.x * w0[idx];
                    a1 += f.y * w1[idx];
                }
        __nv_bfloat162 r = __floats2bfloat162_rn(a0, a1);
        size_t off = ((size_t)((b * 8 + t0 + tt) * 196 + h * 14 + w)) * CADIM + c;
        *(uint32_t*)&g_h2[off] = *(uint32_t*)&r;
    }
}

// ---------------------------------------------------------------------------
// GEMM2: out_tok[M,768] = x_tok + h2[M,384] @ W2^T + b2  (fp32 out, fused residual)
// ---------------------------------------------------------------------------
__global__ __launch_bounds__(256, 2)
void gemm2(const float* __restrict__ x, const float* __restrict__ b2, float* __restrict__ out) {
    __shared__ __nv_bfloat16 As[128 * 40];
    __shared__ __nv_bfloat16 Bs[128 * 40];

    const int tid  = threadIdx.x;
    const int lane = tid & 31;
    const int warp = tid >> 5;
    const int wm   = warp >> 2;
    const int wn   = warp & 3;
    const int bm   = blockIdx.x * 128;
    const int bn   = blockIdx.y * 128;

    const __nv_bfloat16* aptr = g_h2 + (size_t)(bm + (tid >> 1)) * CADIM + (tid & 1) * 16;
    const __nv_bfloat16* bptr = g_W2b + (size_t)(bn + (tid >> 1)) * CADIM + (tid & 1) * 16;
    const int srow  = tid >> 1;
    const int scol0 = (tid & 1) * 16;

    float acc[4][4][4];
#pragma unroll
    for (int i = 0; i < 4; i++)
#pragma unroll
        for (int j = 0; j < 4; j++)
#pragma unroll
            for (int k = 0; k < 4; k++) acc[i][j][k] = 0.f;

    const uint32_t as_base = (uint32_t)__cvta_generic_to_shared(As);
    const uint32_t bs_base = (uint32_t)__cvta_generic_to_shared(Bs);

    for (int kt = 0; kt < CADIM; kt += 32) {
        uint4 av[2], bv[2];
#pragma unroll
        for (int j = 0; j < 2; j++) av[j] = *(const uint4*)(aptr + kt + j * 8);
#pragma unroll
        for (int j = 0; j < 2; j++) bv[j] = *(const uint4*)(bptr + kt + j * 8);

        __syncthreads();
#pragma unroll
        for (int j = 0; j < 2; j++) {
            *(uint4*)&As[srow * 40 + scol0 + j * 8] = av[j];
            *(uint4*)&Bs[srow * 40 + scol0 + j * 8] = bv[j];
        }
        __syncthreads();

#pragma unroll
        for (int ks = 0; ks < 2; ks++) {
            const int kk = ks * 16;
            uint32_t a[4][4], b[4][2];
#pragma unroll
            for (int mf = 0; mf < 4; mf++) {
                int row = wm * 64 + mf * 16 + (lane & 15);
                int col = kk + (lane >> 4) * 8;
                uint32_t addr = as_base + (uint32_t)(row * 40 + col) * 2;
                asm volatile("ldmatrix.sync.aligned.m8n8.x4.shared.b16 {%0,%1,%2,%3}, [%4];\n"
                    : "=r"(a[mf][0]), "=r"(a[mf][1]), "=r"(a[mf][2]), "=r"(a[mf][3]) : "r"(addr));
            }
#pragma unroll
            for (int nf = 0; nf < 4; nf++) {
                int row = wn * 32 + nf * 8 + (lane & 7);
                int col = kk + ((lane >> 3) & 1) * 8;
                uint32_t addr = bs_base + (uint32_t)(row * 40 + col) * 2;
                asm volatile("ldmatrix.sync.aligned.m8n8.x2.shared.b16 {%0,%1}, [%2];\n"
                    : "=r"(b[nf][0]), "=r"(b[nf][1]) : "r"(addr));
            }
#pragma unroll
            for (int mf = 0; mf < 4; mf++)
#pragma unroll
                for (int nf = 0; nf < 4; nf++)
                    asm volatile("mma.sync.aligned.m16n8k16.row.col.f32.bf16.bf16.f32 "
                        "{%0,%1,%2,%3}, {%4,%5,%6,%7}, {%8,%9}, {%0,%1,%2,%3};\n"
                        : "+f"(acc[mf][nf][0]), "+f"(acc[mf][nf][1]),
                          "+f"(acc[mf][nf][2]), "+f"(acc[mf][nf][3])
                        : "r"(a[mf][0]), "r"(a[mf][1]), "r"(a[mf][2]), "r"(a[mf][3]),
                          "r"(b[nf][0]), "r"(b[nf][1]));
        }
    }

    // Epilogue: out = x + acc + b2 at token rows (fused residual, fully writes rows)
#pragma unroll
    for (int mf = 0; mf < 4; mf++) {
        int g0 = bm + wm * 64 + mf * 16 + (lane >> 2);
        int g1 = g0 + 8;
        int bt0 = g0 / LTOK, l0 = g0 - bt0 * LTOK;
        int bt1 = g1 / LTOK, l1 = g1 - bt1 * LTOK;
        size_t base0 = ((size_t)bt0 * LFULL + 1 + l0) * CDIM;
        size_t base1 = ((size_t)bt1 * LFULL + 1 + l1) * CDIM;
#pragma unroll
        for (int nf = 0; nf < 4; nf++) {
            int col = bn + wn * 32 + nf * 8 + (lane & 3) * 2;
            float bb0 = b2[col], bb1 = b2[col + 1];
            float2 x0 = *(const float2*)&x[base0 + col];
            float2 x1 = *(const float2*)&x[base1 + col];
            float2 o0, o1;
            o0.x = x0.x + acc[mf][nf][0] + bb0;
            o0.y = x0.y + acc[mf][nf][1] + bb1;
            o1.x = x1.x + acc[mf][nf][2] + bb0;
            o1.y = x1.y + acc[mf][nf][3] + bb1;
            *(float2*)&out[base0 + col] = o0;
            *(float2*)&out[base1 + col] = o1;
        }
    }
}

// ---------------------------------------------------------------------------
extern "C" void kernel_launch(void* const* d_in, const int* in_sizes, int n_in,
                              void* d_out, int out_size) {
    const float* x  = (const float*)d_in[0];
    const float* W1 = (const float*)d_in[1];
    const float* b1 = (const float*)d_in[2];
    const float* cw = (const float*)d_in[3];
    const float* cb = (const float*)d_in[4];
    const float* W2 = (const float*)d_in[5];
    const float* b2 = (const float*)d_in[6];
    float* out = (float*)d_out;

    cvt_weights<<<(CADIM * CDIM + 255) / 256, 256>>>(W1, W2);
    copy_cls<<<(BATCH * TFR * CDIM + 255) / 256, 256>>>(x, out);
    gemm1<<<dim3(MROWS / 128, CADIM / 128), 256>>>(x, b1);
    dwconv<<<dim3(CADIM / 16, TFR / 2, BATCH), 256>>>(cw, cb);
    gemm2<<<dim3(MROWS / 128, CDIM / 128), 256>>>(x, b2, out);
}

// round 2
// speedup vs baseline: 1.1621x; 1.1621x over previous
#include <cuda_runtime.h>
#include <cuda_bf16.h>
#include <stdint.h>

#define BATCH  32
#define TFR    8
#define CDIM   768
#define CADIM  384
#define LTOK   196
#define LFULL  197
#define MROWS  (BATCH*TFR*LTOK)   // 50176

// Scratch — zero-init BSS device globals (no allocations allowed).
__device__ __nv_bfloat16 g_h1[(size_t)MROWS * CADIM];
__device__ __nv_bfloat16 g_h2[(size_t)MROWS * CADIM];
__device__ __nv_bfloat16 g_W1b[CADIM * CDIM];
__device__ __nv_bfloat16 g_W2b[CDIM * CADIM];

// ---------------------------------------------------------------------------
__global__ void cvt_weights(const float* __restrict__ W1, const float* __restrict__ W2) {
    int i = blockIdx.x * 256 + threadIdx.x;
    if (i < CADIM * CDIM) {
        g_W1b[i] = __float2bfloat16(W1[i]);
        g_W2b[i] = __float2bfloat16(W2[i]);
    }
}

__global__ void copy_cls(const float* __restrict__ x, float* __restrict__ out) {
    int i = blockIdx.x * 256 + threadIdx.x;
    if (i < BATCH * TFR * CDIM) {
        int bt = i / CDIM, c = i - bt * CDIM;
        size_t off = (size_t)bt * LFULL * CDIM + c;
        out[off] = x[off];
    }
}

// ---------------------------------------------------------------------------
// GEMM1: h1[M,384] = bf16( x_tok[M,768] @ W1^T + b1 )
// 128x128x32 tile, double-buffered smem, 1 barrier/iter, LDG prefetch.
// ---------------------------------------------------------------------------
__global__ __launch_bounds__(256, 2)
void gemm1(const float* __restrict__ x, const float* __restrict__ b1) {
    __shared__ __nv_bfloat16 As[2][128 * 40];
    __shared__ __nv_bfloat16 Bs[2][128 * 40];

    const int tid  = threadIdx.x;
    const int lane = tid & 31;
    const int warp = tid >> 5;
    const int wm   = warp >> 2;
    const int wn   = warp & 3;
    const int bm   = blockIdx.x * 128;
    const int bn   = blockIdx.y * 128;

    const int arow  = tid >> 1;
    const int acol0 = (tid & 1) * 16;
    const int growA = bm + arow;
    const int bt    = growA / LTOK;
    const int ltk   = growA - bt * LTOK;
    const float* aptr = x + ((size_t)bt * LFULL + 1 + ltk) * CDIM + acol0;

    const __nv_bfloat16* bptr = g_W1b + (size_t)(bn + (tid >> 1)) * CDIM + (tid & 1) * 16;
    const int brow  = tid >> 1;
    const int bcol0 = (tid & 1) * 16;

    float acc[4][4][4];
#pragma unroll
    for (int i = 0; i < 4; i++)
#pragma unroll
        for (int j = 0; j < 4; j++)
#pragma unroll
            for (int k = 0; k < 4; k++) acc[i][j][k] = 0.f;

    const uint32_t as_base = (uint32_t)__cvta_generic_to_shared(&As[0][0]);
    const uint32_t bs_base = (uint32_t)__cvta_generic_to_shared(&Bs[0][0]);
    const uint32_t bufstride = 128 * 40 * 2;   // bytes per buffer

    float4 av[4];
    uint4  bv[2];
#pragma unroll
    for (int j = 0; j < 4; j++) av[j] = *(const float4*)(aptr + j * 4);
#pragma unroll
    for (int j = 0; j < 2; j++) bv[j] = *(const uint4*)(bptr + j * 8);

    // store buf 0
#pragma unroll
    for (int j = 0; j < 4; j++) {
        __nv_bfloat162 p0 = __floats2bfloat162_rn(av[j].x, av[j].y);
        __nv_bfloat162 p1 = __floats2bfloat162_rn(av[j].z, av[j].w);
        uint2 u; u.x = *(uint32_t*)&p0; u.y = *(uint32_t*)&p1;
        *(uint2*)&As[0][arow * 40 + acol0 + j * 4] = u;
    }
#pragma unroll
    for (int j = 0; j < 2; j++) *(uint4*)&Bs[0][brow * 40 + bcol0 + j * 8] = bv[j];
    __syncthreads();

    int p = 0;
    for (int kt = 0; kt < CDIM; kt += 32) {
        const int ktn = kt + 32;
        if (ktn < CDIM) {
#pragma unroll
            for (int j = 0; j < 4; j++) av[j] = *(const float4*)(aptr + ktn + j * 4);
#pragma unroll
            for (int j = 0; j < 2; j++) bv[j] = *(const uint4*)(bptr + ktn + j * 8);
        }

        const uint32_t asb = as_base + p * bufstride;
        const uint32_t bsb = bs_base + p * bufstride;
#pragma unroll
        for (int ks = 0; ks < 2; ks++) {
            const int kk = ks * 16;
            uint32_t a[4][4], b[4][2];
#pragma unroll
            for (int mf = 0; mf < 4; mf++) {
                int row = wm * 64 + mf * 16 + (lane & 15);
                int col = kk + (lane >> 4) * 8;
                uint32_t addr = asb + (uint32_t)(row * 40 + col) * 2;
                asm volatile("ldmatrix.sync.aligned.m8n8.x4.shared.b16 {%0,%1,%2,%3}, [%4];\n"
                    : "=r"(a[mf][0]), "=r"(a[mf][1]), "=r"(a[mf][2]), "=r"(a[mf][3]) : "r"(addr));
            }
#pragma unroll
            for (int nf = 0; nf < 4; nf++) {
                int row = wn * 32 + nf * 8 + (lane & 7);
                int col = kk + ((lane >> 3) & 1) * 8;
                uint32_t addr = bsb + (uint32_t)(row * 40 + col) * 2;
                asm volatile("ldmatrix.sync.aligned.m8n8.x2.shared.b16 {%0,%1}, [%2];\n"
                    : "=r"(b[nf][0]), "=r"(b[nf][1]) : "r"(addr));
            }
#pragma unroll
            for (int mf = 0; mf < 4; mf++)
#pragma unroll
                for (int nf = 0; nf < 4; nf++)
                    asm volatile("mma.sync.aligned.m16n8k16.row.col.f32.bf16.bf16.f32 "
                        "{%0,%1,%2,%3}, {%4,%5,%6,%7}, {%8,%9}, {%0,%1,%2,%3};\n"
                        : "+f"(acc[mf][nf][0]), "+f"(acc[mf][nf][1]),
                          "+f"(acc[mf][nf][2]), "+f"(acc[mf][nf][3])
                        : "r"(a[mf][0]), "r"(a[mf][1]), "r"(a[mf][2]), "r"(a[mf][3]),
                          "r"(b[nf][0]), "r"(b[nf][1]));
        }

        if (ktn < CDIM) {
            const int q = p ^ 1;
#pragma unroll
            for (int j = 0; j < 4; j++) {
                __nv_bfloat162 p0 = __floats2bfloat162_rn(av[j].x, av[j].y);
                __nv_bfloat162 p1 = __floats2bfloat162_rn(av[j].z, av[j].w);
                uint2 u; u.x = *(uint32_t*)&p0; u.y = *(uint32_t*)&p1;
                *(uint2*)&As[q][arow * 40 + acol0 + j * 4] = u;
            }
#pragma unroll
            for (int j = 0; j < 2; j++) *(uint4*)&Bs[q][brow * 40 + bcol0 + j * 8] = bv[j];
        }
        __syncthreads();
        p ^= 1;
    }

#pragma unroll
    for (int mf = 0; mf < 4; mf++) {
        int r0 = bm + wm * 64 + mf * 16 + (lane >> 2);
#pragma unroll
        for (int nf = 0; nf < 4; nf++) {
            int col = bn + wn * 32 + nf * 8 + (lane & 3) * 2;
            float bb0 = b1[col], bb1 = b1[col + 1];
            __nv_bfloat162 v0 = __floats2bfloat162_rn(acc[mf][nf][0] + bb0, acc[mf][nf][1] + bb1);
            __nv_bfloat162 v1 = __floats2bfloat162_rn(acc[mf][nf][2] + bb0, acc[mf][nf][3] + bb1);
            *(uint32_t*)&g_h1[(size_t)r0 * CADIM + col]       = *(uint32_t*)&v0;
            *(uint32_t*)&g_h1[(size_t)(r0 + 8) * CADIM + col] = *(uint32_t*)&v1;
        }
    }
}

// ---------------------------------------------------------------------------
// Depthwise 3x3x3 conv. Block = (c-chunk 16, batch). Full T volume in dynamic
// smem [10][16][17][8 words] (w-pad 17 -> conflict-free). Thread=(cpair,h,thalf).
// 9 LDS + 27 HFMA2 (bf16x2) per output pair via sliding w-window.
// ---------------------------------------------------------------------------
#define DW_WORDS (10*16*17*8)
__global__ __launch_bounds__(224)
void dwconv(const float* __restrict__ cw, const float* __restrict__ cb) {
    extern __shared__ uint32_t tile[];
    const int tid = threadIdx.x;
    const int c0  = blockIdx.x * 16;
    const int b   = blockIdx.y;

    // zero fill (covers halo)
    uint4 z = make_uint4(0, 0, 0, 0);
    for (int i = tid; i < DW_WORDS / 4; i += 224) ((uint4*)tile)[i] = z;
    __syncthreads();

    // interior fill: 1568 positions x 2 uint4
    for (int i = tid; i < 3136; i += 224) {
        int half = i & 1, pos = i >> 1;
        int t = pos / 196, r = pos - t * 196;
        int hh = r / 14, ww = r - hh * 14;
        int word = (((t + 1) * 16 + (hh + 1)) * 17 + (ww + 1)) * 8 + half * 4;
        uint4 v = *(const uint4*)&g_h1[((size_t)(b * 1568 + pos)) * CADIM + c0 + half * 8];
        *(uint4*)&tile[word] = v;
    }

    const int cp   = tid & 7;
    const int rest = tid >> 3;        // 0..27
    const int h    = rest % 14;
    const int th   = rest / 14;       // 0..1
    const int c    = c0 + cp * 2;

    __nv_bfloat162 wk[27];
#pragma unroll
    for (int j = 0; j < 27; j++)
        wk[j] = __floats2bfloat162_rn(cw[c * 27 + j], cw[(c + 1) * 27 + j]);
    const __nv_bfloat162 bias2 = __floats2bfloat162_rn(cb[c], cb[c + 1]);

    __syncthreads();

    for (int tt = th * 4; tt < th * 4 + 4; ++tt) {
        int base[9];
        uint32_t a0[9], a1[9];
#pragma unroll
        for (int dt = 0; dt < 3; dt++)
#pragma unroll
            for (int dh = 0; dh < 3; dh++) {
                int j = dt * 3 + dh;
                base[j] = (((tt + dt) * 16 + (h + dh)) * 17) * 8 + cp;
                a0[j] = tile[base[j]];
                a1[j] = tile[base[j] + 8];
            }
        size_t obase = ((size_t)((b * 8 + tt) * 196 + h * 14)) * CADIM + c;
#pragma unroll
        for (int w = 0; w < 14; w++) {
            __nv_bfloat162 acc = bias2;
#pragma unroll
            for (int j = 0; j < 9; j++) {
                uint32_t a2 = tile[base[j] + (w + 2) * 8];
                acc = __hfma2(*(__nv_bfloat162*)&a0[j], wk[j * 3 + 0], acc);
                acc = __hfma2(*(__nv_bfloat162*)&a1[j], wk[j * 3 + 1], acc);
                acc = __hfma2(*(__nv_bfloat162*)&a2,    wk[j * 3 + 2], acc);
                a0[j] = a1[j]; a1[j] = a2;
            }
            *(uint32_t*)&g_h2[obase + (size_t)w * CADIM] = *(uint32_t*)&acc;
        }
    }
}

// ---------------------------------------------------------------------------
// GEMM2: out_tok[M,768] = x_tok + h2[M,384] @ W2^T + b2 (fp32, fused residual)
// ---------------------------------------------------------------------------
__global__ __launch_bounds__(256, 2)
void gemm2(const float* __restrict__ x, const float* __restrict__ b2, float* __restrict__ out) {
    __shared__ __nv_bfloat16 As[2][128 * 40];
    __shared__ __nv_bfloat16 Bs[2][128 * 40];

    const int tid  = threadIdx.x;
    const int lane = tid & 31;
    const int warp = tid >> 5;
    const int wm   = warp >> 2;
    const int wn   = warp & 3;
    const int bm   = blockIdx.x * 128;
    const int bn   = blockIdx.y * 128;

    const __nv_bfloat16* aptr = g_h2 + (size_t)(bm + (tid >> 1)) * CADIM + (tid & 1) * 16;
    const __nv_bfloat16* bptr = g_W2b + (size_t)(bn + (tid >> 1)) * CADIM + (tid & 1) * 16;
    const int srow  = tid >> 1;
    const int scol0 = (tid & 1) * 16;

    float acc[4][4][4];
#pragma unroll
    for (int i = 0; i < 4; i++)
#pragma unroll
        for (int j = 0; j < 4; j++)
#pragma unroll
            for (int k = 0; k < 4; k++) acc[i][j][k] = 0.f;

    const uint32_t as_base = (uint32_t)__cvta_generic_to_shared(&As[0][0]);
    const uint32_t bs_base = (uint32_t)__cvta_generic_to_shared(&Bs[0][0]);
    const uint32_t bufstride = 128 * 40 * 2;

    uint4 av[2], bv[2];
#pragma unroll
    for (int j = 0; j < 2; j++) { av[j] = *(const uint4*)(aptr + j * 8); bv[j] = *(const uint4*)(bptr + j * 8); }
#pragma unroll
    for (int j = 0; j < 2; j++) {
        *(uint4*)&As[0][srow * 40 + scol0 + j * 8] = av[j];
        *(uint4*)&Bs[0][srow * 40 + scol0 + j * 8] = bv[j];
    }
    __syncthreads();

    int p = 0;
    for (int kt = 0; kt < CADIM; kt += 32) {
        const int ktn = kt + 32;
        if (ktn < CADIM) {
#pragma unroll
            for (int j = 0; j < 2; j++) { av[j] = *(const uint4*)(aptr + ktn + j * 8); bv[j] = *(const uint4*)(bptr + ktn + j * 8); }
        }

        const uint32_t asb = as_base + p * bufstride;
        const uint32_t bsb = bs_base + p * bufstride;
#pragma unroll
        for (int ks = 0; ks < 2; ks++) {
            const int kk = ks * 16;
            uint32_t a[4][4], b[4][2];
#pragma unroll
            for (int mf = 0; mf < 4; mf++) {
                int row = wm * 64 + mf * 16 + (lane & 15);
                int col = kk + (lane >> 4) * 8;
                uint32_t addr = asb + (uint32_t)(row * 40 + col) * 2;
                asm volatile("ldmatrix.sync.aligned.m8n8.x4.shared.b16 {%0,%1,%2,%3}, [%4];\n"
                    : "=r"(a[mf][0]), "=r"(a[mf][1]), "=r"(a[mf][2]), "=r"(a[mf][3]) : "r"(addr));
            }
#pragma unroll
            for (int nf = 0; nf < 4; nf++) {
                int row = wn * 32 + nf * 8 + (lane & 7);
                int col = kk + ((lane >> 3) & 1) * 8;
                uint32_t addr = bsb + (uint32_t)(row * 40 + col) * 2;
                asm volatile("ldmatrix.sync.aligned.m8n8.x2.shared.b16 {%0,%1}, [%2];\n"
                    : "=r"(b[nf][0]), "=r"(b[nf][1]) : "r"(addr));
            }
#pragma unroll
            for (int mf = 0; mf < 4; mf++)
#pragma unroll
                for (int nf = 0; nf < 4; nf++)
                    asm volatile("mma.sync.aligned.m16n8k16.row.col.f32.bf16.bf16.f32 "
                        "{%0,%1,%2,%3}, {%4,%5,%6,%7}, {%8,%9}, {%0,%1,%2,%3};\n"
                        : "+f"(acc[mf][nf][0]), "+f"(acc[mf][nf][1]),
                          "+f"(acc[mf][nf][2]), "+f"(acc[mf][nf][3])
                        : "r"(a[mf][0]), "r"(a[mf][1]), "r"(a[mf][2]), "r"(a[mf][3]),
                          "r"(b[nf][0]), "r"(b[nf][1]));
        }

        if (ktn < CADIM) {
            const int q = p ^ 1;
#pragma unroll
            for (int j = 0; j < 2; j++) {
                *(uint4*)&As[q][srow * 40 + scol0 + j * 8] = av[j];
                *(uint4*)&Bs[q][srow * 40 + scol0 + j * 8] = bv[j];
            }
        }
        __syncthreads();
        p ^= 1;
    }

#pragma unroll
    for (int mf = 0; mf < 4; mf++) {
        int g0 = bm + wm * 64 + mf * 16 + (lane >> 2);
        int g1 = g0 + 8;
        int bt0 = g0 / LTOK, l0 = g0 - bt0 * LTOK;
        int bt1 = g1 / LTOK, l1 = g1 - bt1 * LTOK;
        size_t base0 = ((size_t)bt0 * LFULL + 1 + l0) * CDIM;
        size_t base1 = ((size_t)bt1 * LFULL + 1 + l1) * CDIM;
#pragma unroll
        for (int nf = 0; nf < 4; nf++) {
            int col = bn + wn * 32 + nf * 8 + (lane & 3) * 2;
            float bb0 = b2[col], bb1 = b2[col + 1];
            float2 x0 = *(const float2*)&x[base0 + col];
            float2 x1 = *(const float2*)&x[base1 + col];
            float2 o0, o1;
            o0.x = x0.x + acc[mf][nf][0] + bb0;
            o0.y = x0.y + acc[mf][nf][1] + bb1;
            o1.x = x1.x + acc[mf][nf][2] + bb0;
            o1.y = x1.y + acc[mf][nf][3] + bb1;
            *(float2*)&out[base0 + col] = o0;
            *(float2*)&out[base1 + col] = o1;
        }
    }
}

// ---------------------------------------------------------------------------
extern "C" void kernel_launch(void* const* d_in, const int* in_sizes, int n_in,
                              void* d_out, int out_size) {
    const float* x  = (const float*)d_in[0];
    const float* W1 = (const float*)d_in[1];
    const float* b1 = (const float*)d_in[2];
    const float* cw = (const float*)d_in[3];
    const float* cb = (const float*)d_in[4];
    const float* W2 = (const float*)d_in[5];
    const float* b2 = (const float*)d_in[6];
    float* out = (float*)d_out;

    static bool attr_done = false;
    if (!attr_done) {
        cudaFuncSetAttribute(dwconv, cudaFuncAttributeMaxDynamicSharedMemorySize, DW_WORDS * 4);
        attr_done = true;
    }

    cvt_weights<<<(CADIM * CDIM + 255) / 256, 256>>>(W1, W2);
    copy_cls<<<(BATCH * TFR * CDIM + 255) / 256, 256>>>(x, out);
    gemm1<<<dim3(MROWS / 128, CADIM / 128), 256>>>(x, b1);
    dwconv<<<dim3(CADIM / 16, BATCH), 224, DW_WORDS * 4>>>(cw, cb);
    gemm2<<<dim3(MROWS / 128, CDIM / 128), 256>>>(x, b2, out);
}

// round 3
// speedup vs baseline: 1.2511x; 1.0766x over previous
#include <cuda_runtime.h>
#include <cuda_bf16.h>
#include <stdint.h>

#define BATCH  32
#define TFR    8
#define CDIM   768
#define CADIM  384
#define LTOK   196
#define LFULL  197
#define MROWS  (BATCH*TFR*LTOK)   // 50176

// Scratch — zero-init BSS device globals (no allocations allowed).
__device__ __nv_bfloat16 g_xb[(size_t)MROWS * CDIM];   // x tokens, bf16, compact
__device__ __nv_bfloat16 g_h1[(size_t)MROWS * CADIM];
__device__ __nv_bfloat16 g_h2[(size_t)MROWS * CADIM];
__device__ __nv_bfloat16 g_W1b[CADIM * CDIM];
__device__ __nv_bfloat16 g_W2b[CDIM * CADIM];

#define CP_ASYNC16(dst, src) \
    asm volatile("cp.async.cg.shared.global [%0], [%1], 16;\n" :: "r"(dst), "l"(src))
#define CP_COMMIT() asm volatile("cp.async.commit_group;\n")
#define CP_WAIT(n)  asm volatile("cp.async.wait_group %0;\n" :: "n"(n))

// ---------------------------------------------------------------------------
__global__ void cvt_weights(const float* __restrict__ W1, const float* __restrict__ W2) {
    int i = blockIdx.x * 256 + threadIdx.x;
    if (i < CADIM * CDIM) {
        g_W1b[i] = __float2bfloat16(W1[i]);
        g_W2b[i] = __float2bfloat16(W2[i]);
    }
}

__global__ void copy_cls(const float* __restrict__ x, float* __restrict__ out) {
    int i = blockIdx.x * 256 + threadIdx.x;
    if (i < BATCH * TFR * CDIM) {
        int bt = i / CDIM, c = i - bt * CDIM;
        size_t off = (size_t)bt * LFULL * CDIM + c;
        out[off] = x[off];
    }
}

// x tokens (skip CLS) -> compact bf16 [MROWS, 768]; 8 elems per thread
__global__ __launch_bounds__(256)
void cvt_x(const float* __restrict__ x) {
    int i = blockIdx.x * 256 + threadIdx.x;   // < MROWS*96
    int row = i / 96;
    int c8  = (i - row * 96) * 8;
    int bt  = row / LTOK;
    int ltk = row - bt * LTOK;
    const float* src = x + ((size_t)bt * LFULL + 1 + ltk) * CDIM + c8;
    float4 f0 = *(const float4*)src;
    float4 f1 = *(const float4*)(src + 4);
    __nv_bfloat162 p0 = __floats2bfloat162_rn(f0.x, f0.y);
    __nv_bfloat162 p1 = __floats2bfloat162_rn(f0.z, f0.w);
    __nv_bfloat162 p2 = __floats2bfloat162_rn(f1.x, f1.y);
    __nv_bfloat162 p3 = __floats2bfloat162_rn(f1.z, f1.w);
    uint4 u;
    u.x = *(uint32_t*)&p0; u.y = *(uint32_t*)&p1;
    u.z = *(uint32_t*)&p2; u.w = *(uint32_t*)&p3;
    *(uint4*)&g_xb[(size_t)row * CDIM + c8] = u;
}

// ---------------------------------------------------------------------------
// Shared GEMM body: C[128,128] tile, 4-stage cp.async pipeline, bf16 x bf16.
// A [M,K] row-major compact, B [N,K] row-major. 8 warps (2x4), warp 64x32.
// ---------------------------------------------------------------------------
#define GSTAGES 4
#define GBUFB   (128 * 40 * 2)   // bytes per stage buffer

struct GemmFrag { float acc[4][4][4]; };

__device__ __forceinline__ void gemm_issue(uint32_t a_dst, const __nv_bfloat16* a_src,
                                           uint32_t b_dst, const __nv_bfloat16* b_src) {
    CP_ASYNC16(a_dst,      a_src);
    CP_ASYNC16(a_dst + 16, a_src + 8);
    CP_ASYNC16(b_dst,      b_src);
    CP_ASYNC16(b_dst + 16, b_src + 8);
}

__device__ __forceinline__ void gemm_compute(uint32_t asb, uint32_t bsb,
                                             int wm, int wn, int lane, GemmFrag& fr) {
#pragma unroll
    for (int ks = 0; ks < 2; ks++) {
        const int kk = ks * 16;
        uint32_t a[4][4], b[4][2];
#pragma unroll
        for (int mf = 0; mf < 4; mf++) {
            int row = wm * 64 + mf * 16 + (lane & 15);
            int col = kk + (lane >> 4) * 8;
            uint32_t addr = asb + (uint32_t)(row * 40 + col) * 2;
            asm volatile("ldmatrix.sync.aligned.m8n8.x4.shared.b16 {%0,%1,%2,%3}, [%4];\n"
                : "=r"(a[mf][0]), "=r"(a[mf][1]), "=r"(a[mf][2]), "=r"(a[mf][3]) : "r"(addr));
        }
#pragma unroll
        for (int nf = 0; nf < 4; nf++) {
            int row = wn * 32 + nf * 8 + (lane & 7);
            int col = kk + ((lane >> 3) & 1) * 8;
            uint32_t addr = bsb + (uint32_t)(row * 40 + col) * 2;
            asm volatile("ldmatrix.sync.aligned.m8n8.x2.shared.b16 {%0,%1}, [%2];\n"
                : "=r"(b[nf][0]), "=r"(b[nf][1]) : "r"(addr));
        }
#pragma unroll
        for (int mf = 0; mf < 4; mf++)
#pragma unroll
            for (int nf = 0; nf < 4; nf++)
                asm volatile("mma.sync.aligned.m16n8k16.row.col.f32.bf16.bf16.f32 "
                    "{%0,%1,%2,%3}, {%4,%5,%6,%7}, {%8,%9}, {%0,%1,%2,%3};\n"
                    : "+f"(fr.acc[mf][nf][0]), "+f"(fr.acc[mf][nf][1]),
                      "+f"(fr.acc[mf][nf][2]), "+f"(fr.acc[mf][nf][3])
                    : "r"(a[mf][0]), "r"(a[mf][1]), "r"(a[mf][2]), "r"(a[mf][3]),
                      "r"(b[nf][0]), "r"(b[nf][1]));
    }
}

// ---------------------------------------------------------------------------
// GEMM1: h1[M,384] = bf16( xb[M,768] @ W1^T + b1 ).  Grid 1-D, bn fastest.
// ---------------------------------------------------------------------------
__global__ __launch_bounds__(256, 2)
void gemm1(const float* __restrict__ b1) {
    __shared__ __nv_bfloat16 As[GSTAGES][128 * 40];
    __shared__ __nv_bfloat16 Bs[GSTAGES][128 * 40];

    const int tid  = threadIdx.x;
    const int lane = tid & 31;
    const int warp = tid >> 5;
    const int wm   = warp >> 2;
    const int wn   = warp & 3;
    const int bm   = (blockIdx.x / 3) * 128;
    const int bn   = (blockIdx.x % 3) * 128;

    const int row  = tid >> 1;
    const int col0 = (tid & 1) * 16;
    const __nv_bfloat16* aptr = g_xb  + (size_t)(bm + row) * CDIM + col0;
    const __nv_bfloat16* bptr = g_W1b + (size_t)(bn + row) * CDIM + col0;
    const uint32_t a_dst0 = (uint32_t)__cvta_generic_to_shared(&As[0][0]) + (uint32_t)(row * 40 + col0) * 2;
    const uint32_t b_dst0 = (uint32_t)__cvta_generic_to_shared(&Bs[0][0]) + (uint32_t)(row * 40 + col0) * 2;

    GemmFrag fr;
#pragma unroll
    for (int i = 0; i < 4; i++)
#pragma unroll
        for (int j = 0; j < 4; j++)
#pragma unroll
            for (int k = 0; k < 4; k++) fr.acc[i][j][k] = 0.f;

    const int KT = CDIM / 32;   // 24
#pragma unroll
    for (int s = 0; s < GSTAGES - 1; s++) {
        gemm_issue(a_dst0 + s * GBUFB, aptr + s * 32, b_dst0 + s * GBUFB, bptr + s * 32);
        CP_COMMIT();
    }

    for (int k = 0; k < KT; k++) {
        CP_WAIT(GSTAGES - 2);
        __syncthreads();
        const int kn = k + GSTAGES - 1;
        if (kn < KT) {
            const int s = kn & (GSTAGES - 1);
            gemm_issue(a_dst0 + s * GBUFB, aptr + kn * 32, b_dst0 + s * GBUFB, bptr + kn * 32);
        }
        CP_COMMIT();
        const int p = k & (GSTAGES - 1);
        gemm_compute((uint32_t)__cvta_generic_to_shared(&As[0][0]) + p * GBUFB,
                     (uint32_t)__cvta_generic_to_shared(&Bs[0][0]) + p * GBUFB,
                     wm, wn, lane, fr);
    }

#pragma unroll
    for (int mf = 0; mf < 4; mf++) {
        int r0 = bm + wm * 64 + mf * 16 + (lane >> 2);
#pragma unroll
        for (int nf = 0; nf < 4; nf++) {
            int col = bn + wn * 32 + nf * 8 + (lane & 3) * 2;
            float bb0 = b1[col], bb1 = b1[col + 1];
            __nv_bfloat162 v0 = __floats2bfloat162_rn(fr.acc[mf][nf][0] + bb0, fr.acc[mf][nf][1] + bb1);
            __nv_bfloat162 v1 = __floats2bfloat162_rn(fr.acc[mf][nf][2] + bb0, fr.acc[mf][nf][3] + bb1);
            *(uint32_t*)&g_h1[(size_t)r0 * CADIM + col]       = *(uint32_t*)&v0;
            *(uint32_t*)&g_h1[(size_t)(r0 + 8) * CADIM + col] = *(uint32_t*)&v1;
        }
    }
}

// ---------------------------------------------------------------------------
// GEMM2: out_tok = x_tok + h2[M,384] @ W2^T + b2 (fp32, fused residual)
// ---------------------------------------------------------------------------
__global__ __launch_bounds__(256, 2)
void gemm2(const float* __restrict__ x, const float* __restrict__ b2, float* __restrict__ out) {
    __shared__ __nv_bfloat16 As[GSTAGES][128 * 40];
    __shared__ __nv_bfloat16 Bs[GSTAGES][128 * 40];

    const int tid  = threadIdx.x;
    const int lane = tid & 31;
    const int warp = tid >> 5;
    const int wm   = warp >> 2;
    const int wn   = warp & 3;
    const int bm   = (blockIdx.x / 6) * 128;
    const int bn   = (blockIdx.x % 6) * 128;

    const int row  = tid >> 1;
    const int col0 = (tid & 1) * 16;
    const __nv_bfloat16* aptr = g_h2  + (size_t)(bm + row) * CADIM + col0;
    const __nv_bfloat16* bptr = g_W2b + (size_t)(bn + row) * CADIM + col0;
    const uint32_t a_dst0 = (uint32_t)__cvta_generic_to_shared(&As[0][0]) + (uint32_t)(row * 40 + col0) * 2;
    const uint32_t b_dst0 = (uint32_t)__cvta_generic_to_shared(&Bs[0][0]) + (uint32_t)(row * 40 + col0) * 2;

    GemmFrag fr;
#pragma unroll
    for (int i = 0; i < 4; i++)
#pragma unroll
        for (int j = 0; j < 4; j++)
#pragma unroll
            for (int k = 0; k < 4; k++) fr.acc[i][j][k] = 0.f;

    const int KT = CADIM / 32;   // 12
#pragma unroll
    for (int s = 0; s < GSTAGES - 1; s++) {
        gemm_issue(a_dst0 + s * GBUFB, aptr + s * 32, b_dst0 + s * GBUFB, bptr + s * 32);
        CP_COMMIT();
    }

    for (int k = 0; k < KT; k++) {
        CP_WAIT(GSTAGES - 2);
        __syncthreads();
        const int kn = k + GSTAGES - 1;
        if (kn < KT) {
            const int s = kn & (GSTAGES - 1);
            gemm_issue(a_dst0 + s * GBUFB, aptr + kn * 32, b_dst0 + s * GBUFB, bptr + kn * 32);
        }
        CP_COMMIT();
        const int p = k & (GSTAGES - 1);
        gemm_compute((uint32_t)__cvta_generic_to_shared(&As[0][0]) + p * GBUFB,
                     (uint32_t)__cvta_generic_to_shared(&Bs[0][0]) + p * GBUFB,
                     wm, wn, lane, fr);
    }

#pragma unroll
    for (int mf = 0; mf < 4; mf++) {
        int g0 = bm + wm * 64 + mf * 16 + (lane >> 2);
        int g1 = g0 + 8;
        int bt0 = g0 / LTOK, l0 = g0 - bt0 * LTOK;
        int bt1 = g1 / LTOK, l1 = g1 - bt1 * LTOK;
        size_t base0 = ((size_t)bt0 * LFULL + 1 + l0) * CDIM;
        size_t base1 = ((size_t)bt1 * LFULL + 1 + l1) * CDIM;
#pragma unroll
        for (int nf = 0; nf < 4; nf++) {
            int col = bn + wn * 32 + nf * 8 + (lane & 3) * 2;
            float bb0 = b2[col], bb1 = b2[col + 1];
            float2 x0 = *(const float2*)&x[base0 + col];
            float2 x1 = *(const float2*)&x[base1 + col];
            float2 o0, o1;
            o0.x = x0.x + fr.acc[mf][nf][0] + bb0;
            o0.y = x0.y + fr.acc[mf][nf][1] + bb1;
            o1.x = x1.x + fr.acc[mf][nf][2] + bb0;
            o1.y = x1.y + fr.acc[mf][nf][3] + bb1;
            *(float2*)&out[base0 + col] = o0;
            *(float2*)&out[base1 + col] = o1;
        }
    }
}

// ---------------------------------------------------------------------------
// Depthwise 3x3x3 conv. Block = (c16, b, t-half). Smem 6x16x17x8 words (52KB).
// Thread = (cpair 8, h 14, tpair 2); 2 t-outputs x 14 w each. 3 accumulators.
// ---------------------------------------------------------------------------
#define DW_WORDS (6*16*17*8)
__global__ __launch_bounds__(224)
void dwconv(const float* __restrict__ cw, const float* __restrict__ cb) {
    extern __shared__ uint32_t tile[];
    const int tid = threadIdx.x;
    const int c0  = blockIdx.x * 16;
    const int b   = blockIdx.y;
    const int t0  = blockIdx.z * 4;     // 4 output t-planes per CTA

    uint4 z = make_uint4(0, 0, 0, 0);
    for (int i = tid; i < DW_WORDS / 4; i += 224) ((uint4*)tile)[i] = z;
    __syncthreads();

    // interior fill: 6 planes (gt = t0-1+tz) x 196 pos x 2 halves
    for (int i = tid; i < 2352; i += 224) {
        int half = i & 1, pos = i >> 1;
        int tz = pos / 196, r = pos - tz * 196;
        int gt = t0 - 1 + tz;
        if ((unsigned)gt < 8u) {
            int hh = r / 14, ww = r - hh * 14;
            int word = ((tz * 16 + (hh + 1)) * 17 + (ww + 1)) * 8 + half * 4;
            uint4 v = *(const uint4*)&g_h1[((size_t)((b * 8 + gt) * 196 + r)) * CADIM + c0 + half * 8];
            *(uint4*)&tile[word] = v;
        }
    }

    const int cp    = tid & 7;
    const int rest  = tid >> 3;         // 0..27
    const int h     = rest % 14;
    const int tpair = rest / 14;        // 0..1
    const int c     = c0 + cp * 2;

    __nv_bfloat162 wk[27];
#pragma unroll
    for (int j = 0; j < 27; j++)
        wk[j] = __floats2bfloat162_rn(cw[c * 27 + j], cw[(c + 1) * 27 + j]);
    const __nv_bfloat162 bias2 = __floats2bfloat162_rn(cb[c], cb[c + 1]);
    const __nv_bfloat162 zero2 = __floats2bfloat162_rn(0.f, 0.f);

    __syncthreads();

#pragma unroll
    for (int tl = 0; tl < 2; tl++) {
        const int lt = tpair * 2 + tl;          // local output t (0..3)
        int base[9];
        uint32_t a0[9], a1[9];
#pragma unroll
        for (int dt = 0; dt < 3; dt++)
#pragma unroll
            for (int dh = 0; dh < 3; dh++) {
                int j = dt * 3 + dh;
                base[j] = (((lt + dt) * 16 + (h + dh)) * 17) * 8 + cp;
                a0[j] = tile[base[j]];
                a1[j] = tile[base[j] + 8];
            }
        size_t obase = ((size_t)((b * 8 + t0 + lt) * 196 + h * 14)) * CADIM + c;
#pragma unroll
        for (int w = 0; w < 14; w++) {
            __nv_bfloat162 s0 = bias2, s1 = zero2, s2 = zero2;
#pragma unroll
            for (int j = 0; j < 9; j++) {
                uint32_t a2 = tile[base[j] + (w + 2) * 8];
                s0 = __hfma2(*(__nv_bfloat162*)&a0[j], wk[j * 3 + 0], s0);
                s1 = __hfma2(*(__nv_bfloat162*)&a1[j], wk[j * 3 + 1], s1);
                s2 = __hfma2(*(__nv_bfloat162*)&a2,    wk[j * 3 + 2], s2);
                a0[j] = a1[j]; a1[j] = a2;
            }
            __nv_bfloat162 acc = __hadd2(__hadd2(s0, s1), s2);
            *(uint32_t*)&g_h2[obase + (size_t)w * CADIM] = *(uint32_t*)&acc;
        }
    }
}

// ---------------------------------------------------------------------------
extern "C" void kernel_launch(void* const* d_in, const int* in_sizes, int n_in,
                              void* d_out, int out_size) {
    const float* x  = (const float*)d_in[0];
    const float* W1 = (const float*)d_in[1];
    const float* b1 = (const float*)d_in[2];
    const float* cw = (const float*)d_in[3];
    const float* cb = (const float*)d_in[4];
    const float* W2 = (const float*)d_in[5];
    const float* b2 = (const float*)d_in[6];
    float* out = (float*)d_out;

    static bool attr_done = false;
    if (!attr_done) {
        cudaFuncSetAttribute(dwconv, cudaFuncAttributeMaxDynamicSharedMemorySize, DW_WORDS * 4);
        attr_done = true;
    }

    cvt_weights<<<(CADIM * CDIM + 255) / 256, 256>>>(W1, W2);
    copy_cls<<<(BATCH * TFR * CDIM + 255) / 256, 256>>>(x, out);
    cvt_x<<<MROWS * 96 / 256, 256>>>(x);
    gemm1<<<(MROWS / 128) * 3, 256>>>(b1);
    dwconv<<<dim3(CADIM / 16, BATCH, 2), 224, DW_WORDS * 4>>>(cw, cb);
    gemm2<<<(MROWS / 128) * 6, 256>>>(x, b2, out);
}